// round 2
// baseline (speedup 1.0000x reference)
#include <cuda_runtime.h>
#include <math.h>

#define NODE_DIM 128
#define MAX_NODES 100000

// Scratch: per-node precomputed UV[n] = [u[n] (128) | v[n] (128)]
__device__ float g_UV[(size_t)MAX_NODES * 256];
// Edge-index dtype flag: 1 if the buffer really holds int64, 0 if int32.
__device__ int g_idx_is64;

// ---------------------------------------------------------------------------
// Dtype detection: with int32 data, int64-reinterpreted values are
// (lo + hi*2^32) with hi ~ U[0,100000) -> out of [0,N) w.p. ~1.
// ---------------------------------------------------------------------------
__global__ void detect_idx_kernel(const void* ei, int n_elems, int N)
{
    const long long* p = (const long long*)ei;
    int k = n_elems < 16 ? n_elems : 16;
    int ok = 1;
    for (int i = 0; i < k; ++i) {
        long long v = p[i];
        if (v < 0 || v >= (long long)N) { ok = 0; break; }
    }
    g_idx_is64 = ok;
}

// ---------------------------------------------------------------------------
// GEMM: UV[N, 256] = x[N, 128] @ Wcat[128, 256]
// Wcat[:, 0:128] = W1[0:128, :],  Wcat[:, 128:256] = W1[128:256, :]
// ---------------------------------------------------------------------------
#define BM 128
#define BN 64
#define BK 32

__global__ void __launch_bounds__(256) gemm_uv_kernel(
    const float* __restrict__ x, const float* __restrict__ W1, int N)
{
    __shared__ float sA[BM][BK + 1];
    __shared__ float sB[BK][BN];

    const int row0 = blockIdx.x * BM;
    const int col0 = blockIdx.y * BN;   // 0,64,128,192 — each block in one W1 half
    const float* Wb = (col0 < NODE_DIM)
                        ? (W1 + col0)
                        : (W1 + NODE_DIM * NODE_DIM + (col0 - NODE_DIM));

    const int tid = threadIdx.x;
    const int tx = tid & 15;
    const int ty = tid >> 4;

    float acc[8][4];
#pragma unroll
    for (int i = 0; i < 8; ++i)
#pragma unroll
        for (int j = 0; j < 4; ++j) acc[i][j] = 0.0f;

    for (int k0 = 0; k0 < NODE_DIM; k0 += BK) {
#pragma unroll
        for (int t = 0; t < (BM * BK) / 256; ++t) {
            int idx = t * 256 + tid;
            int r = idx >> 5;
            int c = idx & 31;
            int gr = row0 + r;
            sA[r][c] = (gr < N) ? x[(size_t)gr * NODE_DIM + k0 + c] : 0.0f;
        }
#pragma unroll
        for (int t = 0; t < (BK * BN) / 256; ++t) {
            int idx = t * 256 + tid;
            int kk = idx >> 6;
            int n  = idx & 63;
            sB[kk][n] = Wb[(size_t)(k0 + kk) * NODE_DIM + n];
        }
        __syncthreads();

#pragma unroll
        for (int k = 0; k < BK; ++k) {
            float4 bv = *(const float4*)&sB[k][tx * 4];
#pragma unroll
            for (int i = 0; i < 8; ++i) {
                float a = sA[ty * 8 + i][k];
                acc[i][0] = fmaf(a, bv.x, acc[i][0]);
                acc[i][1] = fmaf(a, bv.y, acc[i][1]);
                acc[i][2] = fmaf(a, bv.z, acc[i][2]);
                acc[i][3] = fmaf(a, bv.w, acc[i][3]);
            }
        }
        __syncthreads();
    }

#pragma unroll
    for (int i = 0; i < 8; ++i) {
        int gr = row0 + ty * 8 + i;
        if (gr < N) {
            float4 v = make_float4(acc[i][0], acc[i][1], acc[i][2], acc[i][3]);
            *(float4*)&g_UV[(size_t)gr * 256 + col0 + tx * 4] = v;
        }
    }
}

// ---------------------------------------------------------------------------
// Edge pass: one warp per edge.
//   h = relu(u[src] + v[dst] + b1);  out = sigmoid(h . W2 + b2)
// ---------------------------------------------------------------------------
__global__ void __launch_bounds__(256) edge_kernel(
    const void* __restrict__ ei_raw,
    const float* __restrict__ b1,
    const float* __restrict__ W2,
    const float* __restrict__ b2,
    float* __restrict__ out, int E, int N)
{
    int warp = (int)((blockIdx.x * blockDim.x + threadIdx.x) >> 5);
    int lane = threadIdx.x & 31;
    if (warp >= E) return;

    long long s, d;
    if (g_idx_is64) {
        const long long* ei = (const long long*)ei_raw;
        s = __ldg(&ei[warp]);
        d = __ldg(&ei[(size_t)E + warp]);
    } else {
        const int* ei = (const int*)ei_raw;
        s = __ldg(&ei[warp]);
        d = __ldg(&ei[(size_t)E + warp]);
    }
    // Safety clamp: never fault, even if detection were wrong.
    if (s < 0) s = 0; if (s >= N) s = N - 1;
    if (d < 0) d = 0; if (d >= N) d = N - 1;

    float4 u = *(const float4*)&g_UV[(size_t)s * 256 + lane * 4];
    float4 v = *(const float4*)&g_UV[(size_t)d * 256 + 128 + lane * 4];
    float4 bb = __ldg((const float4*)b1 + lane);
    float4 w  = __ldg((const float4*)W2 + lane);

    float h0 = fmaxf(u.x + v.x + bb.x, 0.0f);
    float h1 = fmaxf(u.y + v.y + bb.y, 0.0f);
    float h2 = fmaxf(u.z + v.z + bb.z, 0.0f);
    float h3 = fmaxf(u.w + v.w + bb.w, 0.0f);

    float p = h0 * w.x + h1 * w.y + h2 * w.z + h3 * w.w;
#pragma unroll
    for (int off = 16; off > 0; off >>= 1)
        p += __shfl_xor_sync(0xffffffffu, p, off);

    if (lane == 0) {
        float z = p + __ldg(b2);
        out[warp] = 1.0f / (1.0f + expf(-z));
    }
}

// ---------------------------------------------------------------------------
extern "C" void kernel_launch(void* const* d_in, const int* in_sizes, int n_in,
                              void* d_out, int out_size)
{
    const float* x   = (const float*)d_in[0];
    const void*  ei  = d_in[1];
    const float* W1  = (const float*)d_in[2];
    const float* b1  = (const float*)d_in[3];
    const float* W2  = (const float*)d_in[4];
    const float* b2  = (const float*)d_in[5];
    float* out = (float*)d_out;

    int N = in_sizes[0] / NODE_DIM;   // 100000
    int E = in_sizes[1] / 2;          // 600000

    detect_idx_kernel<<<1, 1>>>(ei, in_sizes[1], N);

    dim3 ggrid((N + BM - 1) / BM, 256 / BN);
    gemm_uv_kernel<<<ggrid, 256>>>(x, W1, N);

    long long total_threads = (long long)E * 32;
    int blocks = (int)((total_threads + 255) / 256);
    edge_kernel<<<blocks, 256>>>(ei, b1, W2, b2, out, E, N);
}

// round 3
// speedup vs baseline: 1.2384x; 1.2384x over previous
#include <cuda_runtime.h>
#include <math.h>

#define NODE_DIM 128
#define MAX_NODES 100000

typedef unsigned long long u64;

// Scratch: per-node precomputed UV[n] = [u[n] (128) | v[n] (128)]
__device__ float g_UV[(size_t)MAX_NODES * 256];
// Edge-index dtype flag: 1 if the buffer really holds int64, 0 if int32.
__device__ int g_idx_is64;

// ---------------------------------------------------------------------------
// Packed f32x2 helpers (sm_103a FFMA2 — PTX-only, ptxas won't auto-fuse)
// ---------------------------------------------------------------------------
__device__ __forceinline__ u64 pack2(float x, float y) {
    u64 r;
    asm("mov.b64 %0, {%1, %2};" : "=l"(r) : "f"(x), "f"(y));
    return r;
}
__device__ __forceinline__ u64 fma2(u64 a, u64 b, u64 c) {
    u64 d;
    asm("fma.rn.f32x2 %0, %1, %2, %3;" : "=l"(d) : "l"(a), "l"(b), "l"(c));
    return d;
}
__device__ __forceinline__ float2 unpack2(u64 v) {
    float2 r;
    asm("mov.b64 {%0, %1}, %2;" : "=f"(r.x), "=f"(r.y) : "l"(v));
    return r;
}

// ---------------------------------------------------------------------------
// Dtype detection: with int32 data, int64-reinterpreted values are
// (lo + hi*2^32) with hi ~ U[0,100000) -> out of [0,N) w.p. ~1.
// ---------------------------------------------------------------------------
__global__ void detect_idx_kernel(const void* ei, int n_elems, int N)
{
    const long long* p = (const long long*)ei;
    int k = n_elems < 16 ? n_elems : 16;
    int ok = 1;
    for (int i = 0; i < k; ++i) {
        long long v = p[i];
        if (v < 0 || v >= (long long)N) { ok = 0; break; }
    }
    g_idx_is64 = ok;
}

// ---------------------------------------------------------------------------
// GEMM: UV[N, 256] = x[N, 128] @ Wcat[128, 256] using packed f32x2 FMAs.
// blockIdx.y selects the W1 half (u vs v). Tile 128x128x16, 256 threads,
// 8x8 microtile split as 2x(4 rows) x 2x(4 cols) for 16B-stride smem reads.
// ---------------------------------------------------------------------------
#define BM 128
#define BN 128
#define BK 16

__global__ void __launch_bounds__(256, 2) gemm_uv_kernel(
    const float* __restrict__ x, const float* __restrict__ W1, int N)
{
    __shared__ float sA[BM][BK + 1];   // [m][k], +1 pad: conflict-free stores
    __shared__ float sB[BK][BN];       // [k][n]

    const int row0 = blockIdx.x * BM;
    const int col0 = blockIdx.y * NODE_DIM;             // 0 or 128 in UV
    const float* Wb = W1 + (size_t)blockIdx.y * NODE_DIM * NODE_DIM;

    const int tid = threadIdx.x;
    const int tx = tid & 15;    // col group
    const int ty = tid >> 4;    // row group

    // acc[rowhalf][i][colhalf][pair] ; pair covers cols (tx*4+2p, tx*4+2p+1)
    u64 acc[2][4][2][2];
#pragma unroll
    for (int rh = 0; rh < 2; ++rh)
#pragma unroll
        for (int i = 0; i < 4; ++i)
#pragma unroll
            for (int ch = 0; ch < 2; ++ch) {
                acc[rh][i][ch][0] = 0ull;
                acc[rh][i][ch][1] = 0ull;
            }

    for (int k0 = 0; k0 < NODE_DIM; k0 += BK) {
        // Load A tile: 128 rows x 16 k = 512 float4 loads, 2 per thread.
#pragma unroll
        for (int t = 0; t < 2; ++t) {
            int idx = t * 256 + tid;
            int r  = idx >> 2;         // 0..127
            int c4 = idx & 3;          // 0..3 (float4 within 16-wide k strip)
            float4 xv = make_float4(0.f, 0.f, 0.f, 0.f);
            int gr = row0 + r;
            if (gr < N) xv = *(const float4*)&x[(size_t)gr * NODE_DIM + k0 + c4 * 4];
            sA[r][c4 * 4 + 0] = xv.x;
            sA[r][c4 * 4 + 1] = xv.y;
            sA[r][c4 * 4 + 2] = xv.z;
            sA[r][c4 * 4 + 3] = xv.w;
        }
        // Load B tile: 16 k x 128 n = 512 float4 loads, 2 per thread.
#pragma unroll
        for (int t = 0; t < 2; ++t) {
            int idx = t * 256 + tid;
            int kk = idx >> 5;         // 0..15
            int c4 = idx & 31;         // 0..31
            float4 wv = *(const float4*)&Wb[(size_t)(k0 + kk) * NODE_DIM + c4 * 4];
            *(float4*)&sB[kk][c4 * 4] = wv;
        }
        __syncthreads();

#pragma unroll
        for (int k = 0; k < BK; ++k) {
            float4 blo = *(const float4*)&sB[k][tx * 4];        // cols tx*4..+3
            float4 bhi = *(const float4*)&sB[k][64 + tx * 4];   // cols 64+tx*4..+3
            u64 bp[2][2];
            bp[0][0] = pack2(blo.x, blo.y);
            bp[0][1] = pack2(blo.z, blo.w);
            bp[1][0] = pack2(bhi.x, bhi.y);
            bp[1][1] = pack2(bhi.z, bhi.w);
#pragma unroll
            for (int rh = 0; rh < 2; ++rh) {
#pragma unroll
                for (int i = 0; i < 4; ++i) {
                    float a = sA[rh * 64 + ty * 4 + i][k];
                    u64 aa = pack2(a, a);
                    acc[rh][i][0][0] = fma2(aa, bp[0][0], acc[rh][i][0][0]);
                    acc[rh][i][0][1] = fma2(aa, bp[0][1], acc[rh][i][0][1]);
                    acc[rh][i][1][0] = fma2(aa, bp[1][0], acc[rh][i][1][0]);
                    acc[rh][i][1][1] = fma2(aa, bp[1][1], acc[rh][i][1][1]);
                }
            }
        }
        __syncthreads();
    }

    // Store to g_UV (row stride 256; this block's cols are [col0, col0+128))
#pragma unroll
    for (int rh = 0; rh < 2; ++rh) {
#pragma unroll
        for (int i = 0; i < 4; ++i) {
            int gr = row0 + rh * 64 + ty * 4 + i;
            if (gr < N) {
#pragma unroll
                for (int ch = 0; ch < 2; ++ch) {
                    float2 lo = unpack2(acc[rh][i][ch][0]);
                    float2 hi = unpack2(acc[rh][i][ch][1]);
                    float4 v = make_float4(lo.x, lo.y, hi.x, hi.y);
                    *(float4*)&g_UV[(size_t)gr * 256 + col0 + ch * 64 + tx * 4] = v;
                }
            }
        }
    }
}

// ---------------------------------------------------------------------------
// Edge pass: one warp per edge.
//   h = relu(u[src] + v[dst] + b1);  out = sigmoid(h . W2 + b2)
// ---------------------------------------------------------------------------
__global__ void __launch_bounds__(256) edge_kernel(
    const void* __restrict__ ei_raw,
    const float* __restrict__ b1,
    const float* __restrict__ W2,
    const float* __restrict__ b2,
    float* __restrict__ out, int E, int N)
{
    int warp = (int)((blockIdx.x * blockDim.x + threadIdx.x) >> 5);
    int lane = threadIdx.x & 31;
    if (warp >= E) return;

    long long s, d;
    if (g_idx_is64) {
        const long long* ei = (const long long*)ei_raw;
        s = __ldg(&ei[warp]);
        d = __ldg(&ei[(size_t)E + warp]);
    } else {
        const int* ei = (const int*)ei_raw;
        s = __ldg(&ei[warp]);
        d = __ldg(&ei[(size_t)E + warp]);
    }
    if (s < 0) s = 0; if (s >= N) s = N - 1;
    if (d < 0) d = 0; if (d >= N) d = N - 1;

    float4 u = *(const float4*)&g_UV[(size_t)s * 256 + lane * 4];
    float4 v = *(const float4*)&g_UV[(size_t)d * 256 + 128 + lane * 4];
    float4 bb = __ldg((const float4*)b1 + lane);
    float4 w  = __ldg((const float4*)W2 + lane);

    float h0 = fmaxf(u.x + v.x + bb.x, 0.0f);
    float h1 = fmaxf(u.y + v.y + bb.y, 0.0f);
    float h2 = fmaxf(u.z + v.z + bb.z, 0.0f);
    float h3 = fmaxf(u.w + v.w + bb.w, 0.0f);

    float p = h0 * w.x + h1 * w.y + h2 * w.z + h3 * w.w;
#pragma unroll
    for (int off = 16; off > 0; off >>= 1)
        p += __shfl_xor_sync(0xffffffffu, p, off);

    if (lane == 0) {
        float z = p + __ldg(b2);
        out[warp] = 1.0f / (1.0f + expf(-z));
    }
}

// ---------------------------------------------------------------------------
extern "C" void kernel_launch(void* const* d_in, const int* in_sizes, int n_in,
                              void* d_out, int out_size)
{
    const float* x   = (const float*)d_in[0];
    const void*  ei  = d_in[1];
    const float* W1  = (const float*)d_in[2];
    const float* b1  = (const float*)d_in[3];
    const float* W2  = (const float*)d_in[4];
    const float* b2  = (const float*)d_in[5];
    float* out = (float*)d_out;

    int N = in_sizes[0] / NODE_DIM;   // 100000
    int E = in_sizes[1] / 2;          // 600000

    detect_idx_kernel<<<1, 1>>>(ei, in_sizes[1], N);

    dim3 ggrid((N + BM - 1) / BM, 2);
    gemm_uv_kernel<<<ggrid, 256>>>(x, W1, N);

    long long total_threads = (long long)E * 32;
    int blocks = (int)((total_threads + 255) / 256);
    edge_kernel<<<blocks, 256>>>(ei, b1, W2, b2, out, E, N);
}